// round 15
// baseline (speedup 1.0000x reference)
#include <cuda_runtime.h>
#include <cuda_fp16.h>
#include <cstdint>

#define T_TOK   4096
#define HS      1024
#define FFN     4096
#define E_NUM   8
#define S_SLOTS (T_TOK * 2)       // 8192
#define BM 256
#define BN 128
#define BK 32
#define KSTH 40                   // A row stride (halves): 80B = 5 groups, coprime 8
#define BSTH 136                  // B row stride (halves): 272B = 17 groups ≡ 1 mod 8
#define NSTAGE 3
#define MAX_TILES (S_SLOTS / BM + E_NUM)   // 40

#define A_BYTES_PER_BUF (BM * KSTH * 2)    // 20480
#define B_BYTES_PER_BUF (BK * BSTH * 2)    // 8704
#define B_OFF (NSTAGE * A_BYTES_PER_BUF)   // 61440
#define SMEM_BYTES (NSTAGE * (A_BYTES_PER_BUF + B_BYTES_PER_BUF))  // 87552

// ---------------- device scratch ----------------
__device__ int    g_cnt[E_NUM];
__device__ int    g_off[E_NUM];
__device__ int    g_ntiles;
__device__ int    g_tile_e[MAX_TILES];
__device__ int    g_tile_mt[MAX_TILES];
__device__ int    g_tok[S_SLOTS];
__device__ float  g_wt [S_SLOTS];
__device__ int    g_slot[S_SLOTS];
__device__ __half g_xh [(size_t)T_TOK * HS];     // 8 MB fp16 x
__device__ __half g_w1h[(size_t)E_NUM * HS * FFN];  // 64 MB fp16 w1 [e][k][n]
__device__ __half g_w2h[(size_t)E_NUM * FFN * HS];  // 64 MB fp16 w2 [e][k][n]
__device__ __half g_H  [(size_t)S_SLOTS * FFN];  // 64 MB hidden acts
__device__ float  g_Y  [(size_t)S_SLOTS * HS];   // 32 MB outputs (k-slice 0)
__device__ float  g_Y2 [(size_t)S_SLOTS * HS];   // 32 MB outputs (k-slice 1)

// ---------------- helpers ----------------
__device__ __forceinline__ uint32_t smem_u32(const void* p) {
    uint32_t a;
    asm("{ .reg .u64 t; cvta.to.shared.u64 t, %1; cvt.u32.u64 %0, t; }"
        : "=r"(a) : "l"(p));
    return a;
}
__device__ __forceinline__ float gelu_tanh(float v) {
    float u = 0.7978845608028654f * (v + 0.044715f * v * v * v);
    return 0.5f * v * (1.0f + tanhf(u));
}
__device__ __forceinline__ void mma_f16(float* c,
                                        uint32_t a0, uint32_t a1,
                                        uint32_t a2, uint32_t a3,
                                        uint32_t b0, uint32_t b1) {
    asm volatile(
        "mma.sync.aligned.m16n8k16.row.col.f32.f16.f16.f32 "
        "{%0,%1,%2,%3}, {%4,%5,%6,%7}, {%8,%9}, {%0,%1,%2,%3};\n"
        : "+f"(c[0]), "+f"(c[1]), "+f"(c[2]), "+f"(c[3])
        : "r"(a0), "r"(a1), "r"(a2), "r"(a3), "r"(b0), "r"(b1));
}
__device__ __forceinline__ void ldsm_x4(uint32_t& r0, uint32_t& r1,
                                        uint32_t& r2, uint32_t& r3, uint32_t a) {
    asm volatile("ldmatrix.sync.aligned.m8n8.x4.shared.b16 {%0,%1,%2,%3}, [%4];\n"
                 : "=r"(r0), "=r"(r1), "=r"(r2), "=r"(r3) : "r"(a));
}
__device__ __forceinline__ void ldsm_x4_t(uint32_t& r0, uint32_t& r1,
                                          uint32_t& r2, uint32_t& r3, uint32_t a) {
    asm volatile("ldmatrix.sync.aligned.m8n8.x4.trans.shared.b16 {%0,%1,%2,%3}, [%4];\n"
                 : "=r"(r0), "=r"(r1), "=r"(r2), "=r"(r3) : "r"(a));
}
__device__ __forceinline__ void cpa16(uint32_t dst, const void* src) {
    asm volatile("cp.async.cg.shared.global [%0], [%1], 16;\n"
                 :: "r"(dst), "l"(src));
}
#define CP_COMMIT() asm volatile("cp.async.commit_group;\n" ::: "memory")
#define CP_WAIT1()  asm volatile("cp.async.wait_group 1;\n" ::: "memory")

// ---------------- routing ----------------
__global__ void zero_cnt_kernel() {
    if (threadIdx.x < E_NUM) g_cnt[threadIdx.x] = 0;
}
__global__ void count_kernel(const int* __restrict__ ei) {
    int i = blockIdx.x * blockDim.x + threadIdx.x;
    if (i < S_SLOTS) atomicAdd(&g_cnt[ei[i]], 1);
}
__global__ void scan_kernel() {
    if (threadIdx.x == 0) {
        int acc = 0, nt = 0;
        for (int e = 0; e < E_NUM; e++) {
            g_off[e] = acc;
            int c = g_cnt[e];
            for (int mt = 0; mt * BM < c; mt++) {
                g_tile_e[nt] = e; g_tile_mt[nt] = mt; nt++;
            }
            acc += c;
        }
        g_ntiles = nt;
    }
}
__global__ void scatter_kernel(const int* __restrict__ ei,
                               const float* __restrict__ ew) {
    int e = blockIdx.x;
    __shared__ int warp_cnt[32];
    int t = threadIdx.x, lane = t & 31, w = t >> 5;
    int running = 0, off = g_off[e];
    for (int c0 = 0; c0 < S_SLOTS; c0 += 1024) {
        int i = c0 + t;
        int match = (ei[i] == e);
        unsigned mask = __ballot_sync(0xffffffffu, match);
        if (lane == 0) warp_cnt[w] = __popc(mask);
        __syncthreads();
        int wbase = 0, total = 0;
#pragma unroll
        for (int j = 0; j < 32; j++) {
            int c = warp_cnt[j];
            if (j < w) wbase += c;
            total += c;
        }
        if (match) {
            int rank = running + wbase + __popc(mask & ((1u << lane) - 1u));
            int slot = off + rank;
            g_tok[slot] = i >> 1;
            g_wt[slot]  = ew[i];
            g_slot[i]   = slot;
        }
        running += total;
        __syncthreads();
    }
}
// f32 -> fp16 cast, 8 elements/thread
__global__ void cast8_kernel(const float* __restrict__ src, __half* __restrict__ dst,
                             int n8) {
    int i = blockIdx.x * blockDim.x + threadIdx.x;
    if (i >= n8) return;
    const float4 a = *(const float4*)(src + (size_t)i * 8);
    const float4 b = *(const float4*)(src + (size_t)i * 8 + 4);
    __half2 h0 = __floats2half2_rn(a.x, a.y);
    __half2 h1 = __floats2half2_rn(a.z, a.w);
    __half2 h2 = __floats2half2_rn(b.x, b.y);
    __half2 h3 = __floats2half2_rn(b.z, b.w);
    uint4 o;
    o.x = *reinterpret_cast<uint32_t*>(&h0);
    o.y = *reinterpret_cast<uint32_t*>(&h1);
    o.z = *reinterpret_cast<uint32_t*>(&h2);
    o.w = *reinterpret_cast<uint32_t*>(&h3);
    *(uint4*)(dst + (size_t)i * 8) = o;
}

// ---------------- shared GEMM stage machinery (macros inline in kernels) ----------------
// A staging: thread t owns tile row t (32 halves = 4x16B)
// B staging: thread t owns k-row t>>3, halves (t&7)*16 .. +16 (2x16B)

// =====================================================================
// GEMM1: H = f16(gelu(gather(x) @ w1h[e]))   block 256x128, warp 64x64
// =====================================================================
__global__ __launch_bounds__(256, 1)
void gemm1_f16(int dummy) {
    const int ty = blockIdx.y;
    if (ty >= g_ntiles) return;
    const int e  = g_tile_e[ty];
    const int mt = g_tile_mt[ty];
    const int nt = blockIdx.x;
    const int cnt  = g_cnt[e];
    const int base = g_off[e] + mt * BM;

    extern __shared__ char smraw[];
    const uint32_t sbase = smem_u32(smraw);

    const int t = threadIdx.x;
    const int arow = (mt * BM + t < cnt) ? g_tok[base + t] : 0;
    const __half* asrc = g_xh + (size_t)arow * HS;
    const int bk = t >> 3, bh = (t & 7) * 16;
    const __half* bsrc = g_w1h + (size_t)e * HS * FFN + (size_t)bk * FFN
                               + nt * BN + bh;
    const uint32_t a_dst = sbase + t * (KSTH * 2);
    const uint32_t b_dst = sbase + B_OFF + bk * (BSTH * 2) + bh * 2;

    const int lane = t & 31, g = lane >> 2, tig = lane & 3;
    const int wm = (t >> 5 & 3) * 64;
    const int wn = (t >> 7) * 64;
    const uint32_t a_frag_half = (uint32_t)((wm + (lane & 15)) * KSTH
                                            + ((lane >> 4) << 3));
    const uint32_t b_frag_half = (uint32_t)((lane & 15) * BSTH + wn
                                            + ((lane >> 4) << 3));

    float acc[4][8][4];
#pragma unroll
    for (int mi = 0; mi < 4; mi++)
#pragma unroll
        for (int ni = 0; ni < 8; ni++)
#pragma unroll
            for (int j = 0; j < 4; j++) acc[mi][ni][j] = 0.f;

    const int S = HS / BK;   // 32 stages
    // prologue: stages 0,1
#pragma unroll
    for (int p = 0; p < NSTAGE - 1; p++) {
        const uint32_t ad = a_dst + p * A_BYTES_PER_BUF;
        const uint32_t bd = b_dst + p * B_BYTES_PER_BUF;
        const __half* as = asrc + p * BK;
        const __half* bs = bsrc + (size_t)(p * BK) * FFN;
        cpa16(ad, as); cpa16(ad + 16, as + 8);
        cpa16(ad + 32, as + 16); cpa16(ad + 48, as + 24);
        cpa16(bd, bs); cpa16(bd + 16, bs + 8);
        CP_COMMIT();
    }

    for (int s = 0; s < S; s++) {
        CP_WAIT1();
        __syncthreads();
        {   // issue stage s+2
            const int sn = s + NSTAGE - 1;
            if (sn < S) {
                const int buf = sn % NSTAGE;
                const uint32_t ad = a_dst + buf * A_BYTES_PER_BUF;
                const uint32_t bd = b_dst + buf * B_BYTES_PER_BUF;
                const __half* as = asrc + sn * BK;
                const __half* bs = bsrc + (size_t)(sn * BK) * FFN;
                cpa16(ad, as); cpa16(ad + 16, as + 8);
                cpa16(ad + 32, as + 16); cpa16(ad + 48, as + 24);
                cpa16(bd, bs); cpa16(bd + 16, bs + 8);
            }
            CP_COMMIT();
        }
        const int buf = s % NSTAGE;
        const uint32_t Ab = sbase + buf * A_BYTES_PER_BUF;
        const uint32_t Bb = sbase + B_OFF + buf * B_BYTES_PER_BUF;
#pragma unroll
        for (int ks = 0; ks < 2; ks++) {
            uint32_t a[4][4], bf[4][4];
#pragma unroll
            for (int mi = 0; mi < 4; mi++)
                ldsm_x4(a[mi][0], a[mi][1], a[mi][2], a[mi][3],
                        Ab + (a_frag_half + mi * 16 * KSTH + ks * 16) * 2);
#pragma unroll
            for (int nc = 0; nc < 4; nc++)
                ldsm_x4_t(bf[nc][0], bf[nc][1], bf[nc][2], bf[nc][3],
                          Bb + (b_frag_half + ks * 16 * BSTH + nc * 16) * 2);
#pragma unroll
            for (int ni = 0; ni < 8; ni++) {
                const uint32_t b0 = bf[ni >> 1][(ni & 1) * 2];
                const uint32_t b1 = bf[ni >> 1][(ni & 1) * 2 + 1];
#pragma unroll
                for (int mi = 0; mi < 4; mi++)
                    mma_f16(acc[mi][ni], a[mi][0], a[mi][1], a[mi][2], a[mi][3],
                            b0, b1);
            }
        }
    }

    // epilogue: gelu -> fp16 into H
    const int ncol0 = nt * BN + wn + 2 * tig;
#pragma unroll
    for (int mi = 0; mi < 4; mi++) {
        const int r0 = wm + mi * 16 + g;
        const int r1 = r0 + 8;
#pragma unroll
        for (int ni = 0; ni < 8; ni++) {
            const int nc = ncol0 + ni * 8;
            if (mt * BM + r0 < cnt) {
                __half2 o = __floats2half2_rn(gelu_tanh(acc[mi][ni][0]),
                                              gelu_tanh(acc[mi][ni][1]));
                *(__half2*)&g_H[(size_t)(base + r0) * FFN + nc] = o;
            }
            if (mt * BM + r1 < cnt) {
                __half2 o = __floats2half2_rn(gelu_tanh(acc[mi][ni][2]),
                                              gelu_tanh(acc[mi][ni][3]));
                *(__half2*)&g_H[(size_t)(base + r1) * FFN + nc] = o;
            }
        }
    }
    (void)dummy;
}

// =====================================================================
// GEMM2: Ypart = wt * (H[:, ksl*2048 : +2048] @ w2h[e] slice)
// grid (HS/BN=8, MAX_TILES, 2) — split-k=2, two output buffers
// =====================================================================
__global__ __launch_bounds__(256, 1)
void gemm2_f16(int dummy) {
    const int ty = blockIdx.y;
    if (ty >= g_ntiles) return;
    const int e  = g_tile_e[ty];
    const int mt = g_tile_mt[ty];
    const int nt = blockIdx.x;
    const int ksl = blockIdx.z;
    const int cnt  = g_cnt[e];
    const int base = g_off[e] + mt * BM;
    const int kbase = ksl * (FFN / 2);

    extern __shared__ char smraw[];
    const uint32_t sbase = smem_u32(smraw);

    const int t = threadIdx.x;
    const bool avalid = (mt * BM + t) < cnt;
    const __half* asrc = g_H + (size_t)(base + (avalid ? t : 0)) * FFN + kbase;
    const int bk = t >> 3, bh = (t & 7) * 16;
    const __half* bsrc = g_w2h + (size_t)e * FFN * HS + (size_t)(kbase + bk) * HS
                               + nt * BN + bh;
    const uint32_t a_dst = sbase + t * (KSTH * 2);
    const uint32_t b_dst = sbase + B_OFF + bk * (BSTH * 2) + bh * 2;

    const int lane = t & 31, g = lane >> 2, tig = lane & 3;
    const int wm = (t >> 5 & 3) * 64;
    const int wn = (t >> 7) * 64;
    const uint32_t a_frag_half = (uint32_t)((wm + (lane & 15)) * KSTH
                                            + ((lane >> 4) << 3));
    const uint32_t b_frag_half = (uint32_t)((lane & 15) * BSTH + wn
                                            + ((lane >> 4) << 3));

    float acc[4][8][4];
#pragma unroll
    for (int mi = 0; mi < 4; mi++)
#pragma unroll
        for (int ni = 0; ni < 8; ni++)
#pragma unroll
            for (int j = 0; j < 4; j++) acc[mi][ni][j] = 0.f;

    const int S = (FFN / 2) / BK;   // 64 stages
#pragma unroll
    for (int p = 0; p < NSTAGE - 1; p++) {
        const uint32_t ad = a_dst + p * A_BYTES_PER_BUF;
        const uint32_t bd = b_dst + p * B_BYTES_PER_BUF;
        const __half* as = asrc + p * BK;
        const __half* bs = bsrc + (size_t)(p * BK) * HS;
        cpa16(ad, as); cpa16(ad + 16, as + 8);
        cpa16(ad + 32, as + 16); cpa16(ad + 48, as + 24);
        cpa16(bd, bs); cpa16(bd + 16, bs + 8);
        CP_COMMIT();
    }

    for (int s = 0; s < S; s++) {
        CP_WAIT1();
        __syncthreads();
        {
            const int sn = s + NSTAGE - 1;
            if (sn < S) {
                const int buf = sn % NSTAGE;
                const uint32_t ad = a_dst + buf * A_BYTES_PER_BUF;
                const uint32_t bd = b_dst + buf * B_BYTES_PER_BUF;
                const __half* as = asrc + sn * BK;
                const __half* bs = bsrc + (size_t)(sn * BK) * HS;
                cpa16(ad, as); cpa16(ad + 16, as + 8);
                cpa16(ad + 32, as + 16); cpa16(ad + 48, as + 24);
                cpa16(bd, bs); cpa16(bd + 16, bs + 8);
            }
            CP_COMMIT();
        }
        const int buf = s % NSTAGE;
        const uint32_t Ab = sbase + buf * A_BYTES_PER_BUF;
        const uint32_t Bb = sbase + B_OFF + buf * B_BYTES_PER_BUF;
#pragma unroll
        for (int ks = 0; ks < 2; ks++) {
            uint32_t a[4][4], bf[4][4];
#pragma unroll
            for (int mi = 0; mi < 4; mi++)
                ldsm_x4(a[mi][0], a[mi][1], a[mi][2], a[mi][3],
                        Ab + (a_frag_half + mi * 16 * KSTH + ks * 16) * 2);
#pragma unroll
            for (int nc = 0; nc < 4; nc++)
                ldsm_x4_t(bf[nc][0], bf[nc][1], bf[nc][2], bf[nc][3],
                          Bb + (b_frag_half + ks * 16 * BSTH + nc * 16) * 2);
#pragma unroll
            for (int ni = 0; ni < 8; ni++) {
                const uint32_t b0 = bf[ni >> 1][(ni & 1) * 2];
                const uint32_t b1 = bf[ni >> 1][(ni & 1) * 2 + 1];
#pragma unroll
                for (int mi = 0; mi < 4; mi++)
                    mma_f16(acc[mi][ni], a[mi][0], a[mi][1], a[mi][2], a[mi][3],
                            b0, b1);
            }
        }
    }

    float* Yout = ksl ? g_Y2 : g_Y;
    const int ncol0 = nt * BN + wn + 2 * tig;
#pragma unroll
    for (int mi = 0; mi < 4; mi++) {
        const int r0 = wm + mi * 16 + g;
        const int r1 = r0 + 8;
#pragma unroll
        for (int ni = 0; ni < 8; ni++) {
            const int nc = ncol0 + ni * 8;
            if (mt * BM + r0 < cnt) {
                float w = g_wt[base + r0];
                float2 o = make_float2(w * acc[mi][ni][0], w * acc[mi][ni][1]);
                *(float2*)&Yout[(size_t)(base + r0) * HS + nc] = o;
            }
            if (mt * BM + r1 < cnt) {
                float w = g_wt[base + r1];
                float2 o = make_float2(w * acc[mi][ni][2], w * acc[mi][ni][3]);
                *(float2*)&Yout[(size_t)(base + r1) * HS + nc] = o;
            }
        }
    }
    (void)dummy;
}

// ---------------- combine: out[t] = sum of 4 partials ----------------
__global__ void combine_kernel(float* __restrict__ out) {
    int i = blockIdx.x * blockDim.x + threadIdx.x;
    if (i >= T_TOK * HS / 4) return;
    int tok = i / (HS / 4);
    int h4  = i - tok * (HS / 4);
    int s0 = g_slot[2 * tok];
    int s1 = g_slot[2 * tok + 1];
    const float4 a0 = *(const float4*)(g_Y  + (size_t)s0 * HS + h4 * 4);
    const float4 a1 = *(const float4*)(g_Y2 + (size_t)s0 * HS + h4 * 4);
    const float4 b0 = *(const float4*)(g_Y  + (size_t)s1 * HS + h4 * 4);
    const float4 b1 = *(const float4*)(g_Y2 + (size_t)s1 * HS + h4 * 4);
    float4 o = make_float4((a0.x + a1.x) + (b0.x + b1.x),
                           (a0.y + a1.y) + (b0.y + b1.y),
                           (a0.z + a1.z) + (b0.z + b1.z),
                           (a0.w + a1.w) + (b0.w + b1.w));
    reinterpret_cast<float4*>(out)[i] = o;
}

// ---------------- launch ----------------
extern "C" void kernel_launch(void* const* d_in, const int* in_sizes, int n_in,
                              void* d_out, int out_size) {
    const float* x  = (const float*)d_in[0];   // [4096, 1024]
    const float* ew = (const float*)d_in[1];   // [4096, 2]
    const int*   ei = (const int*)  d_in[2];   // [4096, 2]
    const float* w1 = (const float*)d_in[3];   // [8, 1024, 4096]
    const float* w2 = (const float*)d_in[4];   // [8, 4096, 1024]
    float* out = (float*)d_out;
    (void)in_sizes; (void)n_in; (void)out_size;

    static bool attr_done = false;
    if (!attr_done) {
        cudaFuncSetAttribute(gemm1_f16,
                             cudaFuncAttributeMaxDynamicSharedMemorySize, SMEM_BYTES);
        cudaFuncSetAttribute(gemm2_f16,
                             cudaFuncAttributeMaxDynamicSharedMemorySize, SMEM_BYTES);
        attr_done = true;
    }

    __half* xh;  cudaGetSymbolAddress((void**)&xh,  g_xh);
    __half* w1h; cudaGetSymbolAddress((void**)&w1h, g_w1h);
    __half* w2h; cudaGetSymbolAddress((void**)&w2h, g_w2h);

    zero_cnt_kernel<<<1, 32>>>();
    count_kernel<<<(S_SLOTS + 255) / 256, 256>>>(ei);
    scan_kernel<<<1, 32>>>();
    scatter_kernel<<<E_NUM, 1024>>>(ei, ew);
    cast8_kernel<<<(T_TOK * HS / 8 + 255) / 256, 256>>>(x, xh, T_TOK * HS / 8);
    cast8_kernel<<<(E_NUM * HS * FFN / 8 + 255) / 256, 256>>>(w1, w1h,
                                                              E_NUM * HS * FFN / 8);
    cast8_kernel<<<(E_NUM * FFN * HS / 8 + 255) / 256, 256>>>(w2, w2h,
                                                              E_NUM * FFN * HS / 8);
    gemm1_f16<<<dim3(FFN / BN, MAX_TILES), 256, SMEM_BYTES>>>(0);
    gemm2_f16<<<dim3(HS / BN, MAX_TILES, 2), 256, SMEM_BYTES>>>(0);
    combine_kernel<<<(T_TOK * HS / 4 + 255) / 256, 256>>>(out);
}

// round 16
// speedup vs baseline: 1.5311x; 1.5311x over previous
#include <cuda_runtime.h>
#include <cuda_fp16.h>
#include <cstdint>

#define T_TOK   4096
#define HS      1024
#define FFN     4096
#define E_NUM   8
#define S_SLOTS (T_TOK * 2)       // 8192
#define BM 256
#define BN 128
#define BK 32
#define KSTH 40                   // A row stride (halves): 20 words, 20r mod 32 distinct
#define BSTH 136                  // B row stride (halves): 68 words, 4r mod 32 distinct
#define MAX_TILES (S_SLOTS / BM + E_NUM)   // 40

#define AS_HALF (BM * KSTH)                // 10240 halves per buffer
#define BS_HALF (BK * BSTH)                // 4352 halves per buffer
#define SMEM_BYTES (2 * (AS_HALF + BS_HALF) * 2)   // 58368

// ---------------- device scratch ----------------
__device__ int    g_cnt[E_NUM];
__device__ int    g_off[E_NUM];
__device__ int    g_ntiles;
__device__ int    g_tile_e[MAX_TILES];
__device__ int    g_tile_mt[MAX_TILES];
__device__ int    g_tok[S_SLOTS];
__device__ float  g_wt [S_SLOTS];
__device__ int    g_slot[S_SLOTS];
__device__ __half g_xh[(size_t)T_TOK * HS];    // 8 MB fp16 x
__device__ __half g_H [(size_t)S_SLOTS * FFN]; // 64 MB hidden acts
__device__ float  g_Y [(size_t)S_SLOTS * HS];  // 32 MB outputs

// ---------------- helpers ----------------
__device__ __forceinline__ uint32_t smem_u32(const void* p) {
    uint32_t a;
    asm("{ .reg .u64 t; cvta.to.shared.u64 t, %1; cvt.u32.u64 %0, t; }"
        : "=r"(a) : "l"(p));
    return a;
}
__device__ __forceinline__ float gelu_tanh(float v) {
    float u = 0.7978845608028654f * (v + 0.044715f * v * v * v);
    return 0.5f * v * (1.0f + tanhf(u));
}
__device__ __forceinline__ void mma_f16(float* c,
                                        uint32_t a0, uint32_t a1,
                                        uint32_t a2, uint32_t a3,
                                        uint32_t b0, uint32_t b1) {
    asm volatile(
        "mma.sync.aligned.m16n8k16.row.col.f32.f16.f16.f32 "
        "{%0,%1,%2,%3}, {%4,%5,%6,%7}, {%8,%9}, {%0,%1,%2,%3};\n"
        : "+f"(c[0]), "+f"(c[1]), "+f"(c[2]), "+f"(c[3])
        : "r"(a0), "r"(a1), "r"(a2), "r"(a3), "r"(b0), "r"(b1));
}
__device__ __forceinline__ void ldsm_x4(uint32_t& r0, uint32_t& r1,
                                        uint32_t& r2, uint32_t& r3, uint32_t a) {
    asm volatile("ldmatrix.sync.aligned.m8n8.x4.shared.b16 {%0,%1,%2,%3}, [%4];\n"
                 : "=r"(r0), "=r"(r1), "=r"(r2), "=r"(r3) : "r"(a));
}
__device__ __forceinline__ void ldsm_x4_t(uint32_t& r0, uint32_t& r1,
                                          uint32_t& r2, uint32_t& r3, uint32_t a) {
    asm volatile("ldmatrix.sync.aligned.m8n8.x4.trans.shared.b16 {%0,%1,%2,%3}, [%4];\n"
                 : "=r"(r0), "=r"(r1), "=r"(r2), "=r"(r3) : "r"(a));
}
// pack 8 consecutive f32 (two float4) into 8 halves
__device__ __forceinline__ uint4 pack8(float4 a, float4 b) {
    __half2 h0 = __floats2half2_rn(a.x, a.y);
    __half2 h1 = __floats2half2_rn(a.z, a.w);
    __half2 h2 = __floats2half2_rn(b.x, b.y);
    __half2 h3 = __floats2half2_rn(b.z, b.w);
    uint4 r;
    r.x = *reinterpret_cast<uint32_t*>(&h0);
    r.y = *reinterpret_cast<uint32_t*>(&h1);
    r.z = *reinterpret_cast<uint32_t*>(&h2);
    r.w = *reinterpret_cast<uint32_t*>(&h3);
    return r;
}

// ---------------- routing ----------------
__global__ void zero_cnt_kernel() {
    if (threadIdx.x < E_NUM) g_cnt[threadIdx.x] = 0;
}
__global__ void count_kernel(const int* __restrict__ ei) {
    int i = blockIdx.x * blockDim.x + threadIdx.x;
    if (i < S_SLOTS) atomicAdd(&g_cnt[ei[i]], 1);
}
__global__ void scan_kernel() {
    if (threadIdx.x == 0) {
        int acc = 0, nt = 0;
        for (int e = 0; e < E_NUM; e++) {
            g_off[e] = acc;
            int c = g_cnt[e];
            for (int mt = 0; mt * BM < c; mt++) {
                g_tile_e[nt] = e; g_tile_mt[nt] = mt; nt++;
            }
            acc += c;
        }
        g_ntiles = nt;
    }
}
__global__ void scatter_kernel(const int* __restrict__ ei,
                               const float* __restrict__ ew) {
    int e = blockIdx.x;
    __shared__ int warp_cnt[32];
    int t = threadIdx.x, lane = t & 31, w = t >> 5;
    int running = 0, off = g_off[e];
    for (int c0 = 0; c0 < S_SLOTS; c0 += 1024) {
        int i = c0 + t;
        int match = (ei[i] == e);
        unsigned mask = __ballot_sync(0xffffffffu, match);
        if (lane == 0) warp_cnt[w] = __popc(mask);
        __syncthreads();
        int wbase = 0, total = 0;
#pragma unroll
        for (int j = 0; j < 32; j++) {
            int c = warp_cnt[j];
            if (j < w) wbase += c;
            total += c;
        }
        if (match) {
            int rank = running + wbase + __popc(mask & ((1u << lane) - 1u));
            int slot = off + rank;
            g_tok[slot] = i >> 1;
            g_wt[slot]  = ew[i];
            g_slot[i]   = slot;
        }
        running += total;
        __syncthreads();
    }
}
// x f32 -> fp16 (8 elements/thread)
__global__ void xcast_kernel(const float* __restrict__ x) {
    int i = blockIdx.x * blockDim.x + threadIdx.x;
    if (i >= T_TOK * HS / 8) return;
    const float4 a = *(const float4*)(x + (size_t)i * 8);
    const float4 b = *(const float4*)(x + (size_t)i * 8 + 4);
    *(uint4*)(g_xh + (size_t)i * 8) = pack8(a, b);
}

// =====================================================================
// GEMM1: H = f16(gelu(gather(x) @ w1[e]))   block 256x128, warp 64x64
// grid (FFN/BN, MAX_TILES), 256 threads, dyn smem 58.4 KB
// =====================================================================
__global__ __launch_bounds__(256, 1)
void gemm1_f16(const float* __restrict__ w1) {
    const int ty = blockIdx.y;
    if (ty >= g_ntiles) return;
    const int e  = g_tile_e[ty];
    const int mt = g_tile_mt[ty];
    const int nt = blockIdx.x;
    const int cnt  = g_cnt[e];
    const int base = g_off[e] + mt * BM;

    extern __shared__ __half sm[];
    __half* As = sm;                    // [2][BM][KSTH]
    __half* Bs = sm + 2 * AS_HALF;      // [2][BK][BSTH]
    const uint32_t As_u = smem_u32(As);
    const uint32_t Bs_u = smem_u32(Bs);
    __shared__ int rows[BM];

    const int t = threadIdx.x;
    rows[t] = (mt * BM + t < cnt) ? g_tok[base + t] : -1;
    __syncthreads();

    // A staging: thread t owns tile row t, 32 k-halves (2 x uint4... 4 x uint4? 32 halves = 4 x 8)
    const int arow = rows[t];
    const __half* aptr = g_xh + (size_t)(arow < 0 ? 0 : arow) * HS;
    // B staging: thread t -> k rows (2*bkk, 2*bkk+1), n cols bn..bn+7 from f32 w1
    const int bkk = t >> 4, bn = (t & 15) * 8;
    const float* bptr = w1 + (size_t)e * HS * FFN
                           + (size_t)(2 * bkk) * FFN + nt * BN + bn;

    const int lane = t & 31, g = lane >> 2, tig = lane & 3;
    const int wm = (t >> 5 & 3) * 64;
    const int wn = (t >> 7) * 64;
    const uint32_t a_frag = (uint32_t)((wm + (lane & 15)) * KSTH + ((lane >> 4) << 3));
    const uint32_t b_frag = (uint32_t)((lane & 15) * BSTH + wn + ((lane >> 4) << 3));

    float acc[4][8][4];
#pragma unroll
    for (int mi = 0; mi < 4; mi++)
#pragma unroll
        for (int ni = 0; ni < 8; ni++)
#pragma unroll
            for (int j = 0; j < 4; j++) acc[mi][ni][j] = 0.f;

    uint4 ua[4];
    float4 rb00, rb01, rb10, rb11;
    {
        const uint4 uz = make_uint4(0, 0, 0, 0);
#pragma unroll
        for (int q = 0; q < 4; q++)
            ua[q] = (arow >= 0) ? *(const uint4*)(aptr + q * 8) : uz;
        rb00 = *(const float4*)(bptr);
        rb01 = *(const float4*)(bptr + 4);
        rb10 = *(const float4*)(bptr + FFN);
        rb11 = *(const float4*)(bptr + FFN + 4);
    }
#pragma unroll
    for (int q = 0; q < 4; q++)
        *(uint4*)&As[t * KSTH + q * 8] = ua[q];
    *(uint4*)&Bs[(2 * bkk) * BSTH + bn]     = pack8(rb00, rb01);
    *(uint4*)&Bs[(2 * bkk + 1) * BSTH + bn] = pack8(rb10, rb11);
    __syncthreads();

    const int S = HS / BK;   // 32 stages
    for (int s = 0; s < S; s++) {
        const int buf = s & 1;
        const bool more = (s + 1 < S);
        if (more) {
            const int k0 = (s + 1) * BK;
            const uint4 uz = make_uint4(0, 0, 0, 0);
#pragma unroll
            for (int q = 0; q < 4; q++)
                ua[q] = (arow >= 0) ? *(const uint4*)(aptr + k0 + q * 8) : uz;
            const float* bp = bptr + (size_t)k0 * FFN;
            rb00 = *(const float4*)(bp);
            rb01 = *(const float4*)(bp + 4);
            rb10 = *(const float4*)(bp + FFN);
            rb11 = *(const float4*)(bp + FFN + 4);
        }
        const uint32_t Ab = As_u + (buf * AS_HALF) * 2;
        const uint32_t Bb = Bs_u + (buf * BS_HALF) * 2;
#pragma unroll
        for (int ks = 0; ks < 2; ks++) {
            uint32_t a[4][4], bf[4][4];
#pragma unroll
            for (int mi = 0; mi < 4; mi++)
                ldsm_x4(a[mi][0], a[mi][1], a[mi][2], a[mi][3],
                        Ab + (a_frag + mi * 16 * KSTH + ks * 16) * 2);
#pragma unroll
            for (int nc = 0; nc < 4; nc++)
                ldsm_x4_t(bf[nc][0], bf[nc][1], bf[nc][2], bf[nc][3],
                          Bb + (b_frag + ks * 16 * BSTH + nc * 16) * 2);
#pragma unroll
            for (int ni = 0; ni < 8; ni++) {
                const uint32_t b0 = bf[ni >> 1][(ni & 1) * 2];
                const uint32_t b1 = bf[ni >> 1][(ni & 1) * 2 + 1];
#pragma unroll
                for (int mi = 0; mi < 4; mi++)
                    mma_f16(acc[mi][ni], a[mi][0], a[mi][1], a[mi][2], a[mi][3],
                            b0, b1);
            }
        }
        if (more) {
            const int nb = buf ^ 1;
            __half* An = As + nb * AS_HALF;
            __half* Bn = Bs + nb * BS_HALF;
#pragma unroll
            for (int q = 0; q < 4; q++)
                *(uint4*)&An[t * KSTH + q * 8] = ua[q];
            *(uint4*)&Bn[(2 * bkk) * BSTH + bn]     = pack8(rb00, rb01);
            *(uint4*)&Bn[(2 * bkk + 1) * BSTH + bn] = pack8(rb10, rb11);
            __syncthreads();
        }
    }

    // epilogue: gelu -> fp16 into H
    const int ncol0 = nt * BN + wn + 2 * tig;
#pragma unroll
    for (int mi = 0; mi < 4; mi++) {
        const int r0 = wm + mi * 16 + g;
        const int r1 = r0 + 8;
#pragma unroll
        for (int ni = 0; ni < 8; ni++) {
            const int nc = ncol0 + ni * 8;
            if (mt * BM + r0 < cnt) {
                __half2 o = __floats2half2_rn(gelu_tanh(acc[mi][ni][0]),
                                              gelu_tanh(acc[mi][ni][1]));
                *(__half2*)&g_H[(size_t)(base + r0) * FFN + nc] = o;
            }
            if (mt * BM + r1 < cnt) {
                __half2 o = __floats2half2_rn(gelu_tanh(acc[mi][ni][2]),
                                              gelu_tanh(acc[mi][ni][3]));
                *(__half2*)&g_H[(size_t)(base + r1) * FFN + nc] = o;
            }
        }
    }
}

// =====================================================================
// GEMM2: Y = wt * (H @ w2[e])   block 256x128, warp 64x64
// grid (HS/BN, MAX_TILES), 256 threads, dyn smem 58.4 KB
// =====================================================================
__global__ __launch_bounds__(256, 1)
void gemm2_f16(const float* __restrict__ w2) {
    const int ty = blockIdx.y;
    if (ty >= g_ntiles) return;
    const int e  = g_tile_e[ty];
    const int mt = g_tile_mt[ty];
    const int nt = blockIdx.x;
    const int cnt  = g_cnt[e];
    const int base = g_off[e] + mt * BM;

    extern __shared__ __half sm[];
    __half* As = sm;
    __half* Bs = sm + 2 * AS_HALF;
    const uint32_t As_u = smem_u32(As);
    const uint32_t Bs_u = smem_u32(Bs);

    const int t = threadIdx.x;
    const bool avalid = (mt * BM + t) < cnt;
    const __half* aptr = g_H + (size_t)(base + (avalid ? t : 0)) * FFN;
    const int bkk = t >> 4, bn = (t & 15) * 8;
    const float* bptr = w2 + (size_t)e * FFN * HS
                           + (size_t)(2 * bkk) * HS + nt * BN + bn;

    const int lane = t & 31, g = lane >> 2, tig = lane & 3;
    const int wm = (t >> 5 & 3) * 64;
    const int wn = (t >> 7) * 64;
    const uint32_t a_frag = (uint32_t)((wm + (lane & 15)) * KSTH + ((lane >> 4) << 3));
    const uint32_t b_frag = (uint32_t)((lane & 15) * BSTH + wn + ((lane >> 4) << 3));

    float acc[4][8][4];
#pragma unroll
    for (int mi = 0; mi < 4; mi++)
#pragma unroll
        for (int ni = 0; ni < 8; ni++)
#pragma unroll
            for (int j = 0; j < 4; j++) acc[mi][ni][j] = 0.f;

    uint4 ua[4];
    float4 rb00, rb01, rb10, rb11;
    {
        const uint4 uz = make_uint4(0, 0, 0, 0);
#pragma unroll
        for (int q = 0; q < 4; q++)
            ua[q] = avalid ? *(const uint4*)(aptr + q * 8) : uz;
        rb00 = *(const float4*)(bptr);
        rb01 = *(const float4*)(bptr + 4);
        rb10 = *(const float4*)(bptr + HS);
        rb11 = *(const float4*)(bptr + HS + 4);
    }
#pragma unroll
    for (int q = 0; q < 4; q++)
        *(uint4*)&As[t * KSTH + q * 8] = ua[q];
    *(uint4*)&Bs[(2 * bkk) * BSTH + bn]     = pack8(rb00, rb01);
    *(uint4*)&Bs[(2 * bkk + 1) * BSTH + bn] = pack8(rb10, rb11);
    __syncthreads();

    const int S = FFN / BK;   // 128 stages
    for (int s = 0; s < S; s++) {
        const int buf = s & 1;
        const bool more = (s + 1 < S);
        if (more) {
            const int k0 = (s + 1) * BK;
            const uint4 uz = make_uint4(0, 0, 0, 0);
#pragma unroll
            for (int q = 0; q < 4; q++)
                ua[q] = avalid ? *(const uint4*)(aptr + k0 + q * 8) : uz;
            const float* bp = bptr + (size_t)k0 * HS;
            rb00 = *(const float4*)(bp);
            rb01 = *(const float4*)(bp + 4);
            rb10 = *(const float4*)(bp + HS);
            rb11 = *(const float4*)(bp + HS + 4);
        }
        const uint32_t Ab = As_u + (buf * AS_HALF) * 2;
        const uint32_t Bb = Bs_u + (buf * BS_HALF) * 2;
#pragma unroll
        for (int ks = 0; ks < 2; ks++) {
            uint32_t a[4][4], bf[4][4];
#pragma unroll
            for (int mi = 0; mi < 4; mi++)
                ldsm_x4(a[mi][0], a[mi][1], a[mi][2], a[mi][3],
                        Ab + (a_frag + mi * 16 * KSTH + ks * 16) * 2);
#pragma unroll
            for (int nc = 0; nc < 4; nc++)
                ldsm_x4_t(bf[nc][0], bf[nc][1], bf[nc][2], bf[nc][3],
                          Bb + (b_frag + ks * 16 * BSTH + nc * 16) * 2);
#pragma unroll
            for (int ni = 0; ni < 8; ni++) {
                const uint32_t b0 = bf[ni >> 1][(ni & 1) * 2];
                const uint32_t b1 = bf[ni >> 1][(ni & 1) * 2 + 1];
#pragma unroll
                for (int mi = 0; mi < 4; mi++)
                    mma_f16(acc[mi][ni], a[mi][0], a[mi][1], a[mi][2], a[mi][3],
                            b0, b1);
            }
        }
        if (more) {
            const int nb = buf ^ 1;
            __half* An = As + nb * AS_HALF;
            __half* Bn = Bs + nb * BS_HALF;
#pragma unroll
            for (int q = 0; q < 4; q++)
                *(uint4*)&An[t * KSTH + q * 8] = ua[q];
            *(uint4*)&Bn[(2 * bkk) * BSTH + bn]     = pack8(rb00, rb01);
            *(uint4*)&Bn[(2 * bkk + 1) * BSTH + bn] = pack8(rb10, rb11);
            __syncthreads();
        }
    }

    // epilogue: gate-weight scale -> f32 Y
    const int ncol0 = nt * BN + wn + 2 * tig;
#pragma unroll
    for (int mi = 0; mi < 4; mi++) {
        const int r0 = wm + mi * 16 + g;
        const int r1 = r0 + 8;
#pragma unroll
        for (int ni = 0; ni < 8; ni++) {
            const int nc = ncol0 + ni * 8;
            if (mt * BM + r0 < cnt) {
                float w = g_wt[base + r0];
                float2 o = make_float2(w * acc[mi][ni][0], w * acc[mi][ni][1]);
                *(float2*)&g_Y[(size_t)(base + r0) * HS + nc] = o;
            }
            if (mt * BM + r1 < cnt) {
                float w = g_wt[base + r1];
                float2 o = make_float2(w * acc[mi][ni][2], w * acc[mi][ni][3]);
                *(float2*)&g_Y[(size_t)(base + r1) * HS + nc] = o;
            }
        }
    }
}

// ---------------- combine: out[t] = Y[slot(t,0)] + Y[slot(t,1)] ----------------
__global__ void combine_kernel(float* __restrict__ out) {
    int i = blockIdx.x * blockDim.x + threadIdx.x;
    if (i >= T_TOK * HS / 4) return;
    int tok = i / (HS / 4);
    int h4  = i - tok * (HS / 4);
    int s0 = g_slot[2 * tok];
    int s1 = g_slot[2 * tok + 1];
    const float4 y0 = *(const float4*)(g_Y + (size_t)s0 * HS + h4 * 4);
    const float4 y1 = *(const float4*)(g_Y + (size_t)s1 * HS + h4 * 4);
    float4 o = make_float4(y0.x + y1.x, y0.y + y1.y, y0.z + y1.z, y0.w + y1.w);
    reinterpret_cast<float4*>(out)[i] = o;
}

// ---------------- launch ----------------
extern "C" void kernel_launch(void* const* d_in, const int* in_sizes, int n_in,
                              void* d_out, int out_size) {
    const float* x  = (const float*)d_in[0];   // [4096, 1024]
    const float* ew = (const float*)d_in[1];   // [4096, 2]
    const int*   ei = (const int*)  d_in[2];   // [4096, 2]
    const float* w1 = (const float*)d_in[3];   // [8, 1024, 4096]
    const float* w2 = (const float*)d_in[4];   // [8, 4096, 1024]
    float* out = (float*)d_out;
    (void)in_sizes; (void)n_in; (void)out_size;

    static bool attr_done = false;
    if (!attr_done) {
        cudaFuncSetAttribute(gemm1_f16,
                             cudaFuncAttributeMaxDynamicSharedMemorySize, SMEM_BYTES);
        cudaFuncSetAttribute(gemm2_f16,
                             cudaFuncAttributeMaxDynamicSharedMemorySize, SMEM_BYTES);
        attr_done = true;
    }

    zero_cnt_kernel<<<1, 32>>>();
    count_kernel<<<(S_SLOTS + 255) / 256, 256>>>(ei);
    scan_kernel<<<1, 32>>>();
    scatter_kernel<<<E_NUM, 1024>>>(ei, ew);
    xcast_kernel<<<(T_TOK * HS / 8 + 255) / 256, 256>>>(x);
    gemm1_f16<<<dim3(FFN / BN, MAX_TILES), 256, SMEM_BYTES>>>(w1);
    gemm2_f16<<<dim3(HS / BN, MAX_TILES), 256, SMEM_BYTES>>>(w2);
    combine_kernel<<<(T_TOK * HS / 4 + 255) / 256, 256>>>(out);
}